// round 7
// baseline (speedup 1.0000x reference)
#include <cuda_runtime.h>
#include <type_traits>
#include <cstddef>

namespace so3 {

constexpr int LMAX  = 8;
constexpr int NCOEF = (LMAX + 1) * (LMAX + 1);   // 81 raw inputs per batch per array
constexpr int NCMP  = 45;                        // compact m>=0 coefficient count
constexpr int TPB   = 128;

// ---------------- compile-time math ----------------
__host__ __device__ constexpr double fact(int n) { double r = 1.0; for (int i = 2; i <= n; ++i) r *= (double)i; return r; }
__host__ __device__ constexpr double csqrt(double x) {
    if (x <= 0.0) return 0.0;
    double g = x > 1.0 ? x : 1.0;
    for (int i = 0; i < 64; ++i) g = 0.5 * (g + x / g);
    return g;
}
__host__ __device__ constexpr int iabs(int x) { return x < 0 ? -x : x; }
__host__ __device__ constexpr int imin(int a, int b) { return a < b ? a : b; }
__host__ __device__ constexpr int imax(int a, int b) { return a > b ? a : b; }
__host__ __device__ constexpr int cpos(int l, int m) { return l * (l + 1) / 2 + m; }   // 0..44

// Clebsch-Gordan <j1 m1 j2 m2 | j3 m3>, Racah formula (matches reference)
__host__ __device__ constexpr double cg(int j1, int m1, int j2, int m2, int j3, int m3) {
    if (m1 + m2 != m3) return 0.0;
    if (j3 < iabs(j1 - j2) || j3 > j1 + j2) return 0.0;
    if (iabs(m1) > j1 || iabs(m2) > j2 || iabs(m3) > j3) return 0.0;
    double pre = csqrt((2.0 * j3 + 1.0) * fact(j1 + j2 - j3) * fact(j1 - j2 + j3) *
                       fact(-j1 + j2 + j3) / fact(j1 + j2 + j3 + 1));
    pre *= csqrt(fact(j1 + m1) * fact(j1 - m1) * fact(j2 + m2) * fact(j2 - m2) *
                 fact(j3 + m3) * fact(j3 - m3));
    int kmin = imax(0, imax(j2 - j3 - m1, j1 - j3 + m2));
    int kmax = imin(j1 + j2 - j3, imin(j1 - m1, j2 + m2));
    double s = 0.0;
    for (int k = kmin; k <= kmax; ++k) {
        double d = fact(k) * fact(j1 + j2 - j3 - k) * fact(j1 - m1 - k) *
                   fact(j2 + m2 - k) * fact(j3 - j2 + m1 + k) * fact(j3 - j1 - m2 + k);
        s += ((k & 1) ? -1.0 : 1.0) / d;
    }
    return pre * s;
}

// ---------------- output index maps (mirror reference builders) ----------------
__host__ __device__ constexpr int full_index(int a, int b, int c) {
    int idx = 0;
    for (int l1 = 0; l1 <= LMAX; ++l1)
        for (int l2 = l1; l2 <= LMAX; ++l2)
            for (int lv = l2 - l1; lv <= imin(l1 + l2, LMAX); ++lv) {
                if (l1 == a && l2 == b && lv == c) return idx;
                ++idx;
            }
    return -1;
}
__host__ __device__ constexpr int count_full() {
    int idx = 0;
    for (int l1 = 0; l1 <= LMAX; ++l1)
        for (int l2 = l1; l2 <= LMAX; ++l2)
            for (int lv = l2 - l1; lv <= imin(l1 + l2, LMAX); ++lv) ++idx;
    return idx;
}
constexpr int NFULL = count_full();
static_assert(NFULL == 215, "FULL map size mismatch");

__host__ __device__ constexpr int power_index_impl(int a, int b, int c) {
    int idx = 0;
    for (int l2 = 2; l2 <= LMAX; ++l2) {
        if (a == 1 && b == l2 && c == l2 - 1) return idx;
        ++idx;
        if (l2 >= 4 && (l2 - 1) + 1 <= imin(l2 + 1, LMAX)) {
            if (a == 1 && b == l2 && c == l2) return idx;
            ++idx;
        }
    }
    for (int l2 = 3; l2 <= LMAX; ++l2) {
        if (a == 2 && b == l2 && c == l2 - 2) return idx;
        ++idx;
        if ((l2 - 2) + 1 <= imin(l2 + 2, LMAX)) {
            if (a == 2 && b == l2 && c == l2 - 1) return idx;
            ++idx;
        }
    }
    if (LMAX >= 3) {
        if (a == 3 && b == 3 && c == 2) return idx;
        ++idx;
    }
    for (int l2 = 4; l2 <= LMAX; ++l2) {
        if (a == 3 && b == l2 && c == l2 - 3) return idx;
        ++idx;
        if ((l2 % 2 == 1) && l2 >= 5) {
            if ((l2 - 3) + 1 <= imin(l2 + 3, LMAX)) {
                if (a == 3 && b == l2 && c == l2 - 2) return idx;
                ++idx;
            }
            if ((l2 - 3) + 2 <= imin(l2 + 3, LMAX)) {
                if (a == 3 && b == l2 && c == l2 - 1) return idx;
                ++idx;
            }
        }
    }
    return 1000 + idx;
}
__host__ __device__ constexpr int power_index(int a, int b, int c) {
    return power_index_impl(a, b, c) >= 1000 ? -1 : power_index_impl(a, b, c);
}
constexpr int NPOWER = power_index_impl(-9, -9, -9) - 1000;
static_assert(NPOWER == 34, "POWER map size mismatch");
constexpr int NOUT = NFULL + NPOWER;   // 249

// ---------------- static-for ----------------
template <int I, int N, class F>
__device__ __forceinline__ void sfor(F&& f) {
    if constexpr (I < N) {
        f(std::integral_constant<int, I>{});
        sfor<I + 1, N>(f);
    }
}

// Accessors over per-pair register rows (float2 = {re, im}), any m in [-L+1, L-1].
// F_l^{-m} = (-1)^m conj(F_l^m)
template <int m, int L>
__device__ __forceinline__ float rowre(const float2 (&f)[L]) {
    if constexpr (m >= 0) return f[m].x;
    else if constexpr ((-m) & 1) return -f[-m].x;
    else return f[-m].x;
}
template <int m, int L>
__device__ __forceinline__ float rowim(const float2 (&f)[L]) {
    if constexpr (m >= 0) return f[m].y;
    else if constexpr ((-m) & 1) return f[-m].y;
    else return -f[-m].y;
}

// ---------------- kernel ----------------
__global__ void __launch_bounds__(TPB, 4) bispec_kernel(
    const float* __restrict__ cre, const float* __restrict__ cim,
    float* __restrict__ out, int batch)
{
    // Interleaved compact coefficients: cf[thread][cpos(l,m)] = {re, im}, m >= 0 only.
    // Stride 45 float2 (=360B) per thread: half-warp LDS.64 is bank-conflict-free.
    __shared__ float2 cf[TPB * NCMP];

    const int blk_base = blockIdx.x * TPB;
    const int b = blk_base + threadIdx.x;

    // ---- coalesced load + compaction into SMEM ----
    {
        const float* gre = cre + (size_t)blk_base * NCOEF;
        const float* gim = cim + (size_t)blk_base * NCOEF;
        for (int g = threadIdx.x; g < TPB * NCOEF; g += TPB) {
            const int bloc = g / NCOEF;
            if (blk_base + bloc < batch) {
                const int c = g - bloc * NCOEF;
                const int l = c / (LMAX + 1);
                const int m = c - l * (LMAX + 1);
                if (m <= l) {
                    cf[bloc * NCMP + cpos(l, m)] = make_float2(gre[g], gim[g]);
                }
            }
        }
    }
    __syncthreads();

    if (b >= batch) return;

    const float2* __restrict__ myc = cf + threadIdx.x * NCMP;
    float* __restrict__ ob = out + (size_t)b * NOUT;

    // ---- fully unrolled bispectrum; coefficients fetched from SMEM per pair ----
    sfor<0, LMAX + 1>([&](auto L1c) {
        constexpr int l1 = decltype(L1c)::value;

        // load F_l1 row once per l1 (reused across all l2)
        float2 f1[l1 + 1];
        sfor<0, l1 + 1>([&](auto Mc) {
            constexpr int m = decltype(Mc)::value;
            f1[m] = myc[cpos(l1, m)];
        });

        sfor<l1, LMAX + 1>([&](auto L2c) {
            constexpr int l2 = decltype(L2c)::value;
            constexpr int lomin = l2 - l1;
            constexpr int lomax = imin(l1 + l2, LMAX);
            constexpr int nlo = lomax - lomin + 1;

            // load F_l2 row for this pair
            float2 f2[l2 + 1];
            sfor<0, l2 + 1>([&](auto Mc) {
                constexpr int m = decltype(Mc)::value;
                f2[m] = myc[cpos(l2, m)];
            });

            float beta[nlo];
            float pw[nlo];
            sfor<0, nlo>([&](auto Ic) {
                constexpr int i = decltype(Ic)::value;
                beta[i] = 0.f; pw[i] = 0.f;
            });

            sfor<-(l1 + l2), l1 + l2 + 1>([&](auto MMc) {
                constexpr int M = decltype(MMc)::value;
                constexpr int lstart = imax(lomin, iabs(M));
                if constexpr (lstart <= lomax) {
                    constexpr int ng = lomax - lstart + 1;
                    float gre[ng], gim[ng];
                    sfor<0, ng>([&](auto Ic) {
                        constexpr int i = decltype(Ic)::value;
                        gre[i] = 0.f; gim[i] = 0.f;
                    });

                    constexpr int m1lo = imax(-l1, M - l2);
                    constexpr int m1hi = imin(l1, M + l2);
                    sfor<m1lo, m1hi + 1>([&](auto M1c) {
                        constexpr int m1 = decltype(M1c)::value;
                        constexpr int m2 = M - m1;
                        // l1==l2: fold (m1,m2)+(m2,m1), keep m1<=m2 only
                        if constexpr (!(l1 == l2 && m1 > m2)) {
                            float are = rowre<m1>(f1), aim = rowim<m1>(f1);
                            float bre = rowre<m2>(f2), bim = rowim<m2>(f2);
                            float p_re = are * bre - aim * bim;
                            float p_im = are * bim + aim * bre;
                            sfor<lstart, lomax + 1>([&](auto LOc) {
                                constexpr int lo = decltype(LOc)::value;
                                constexpr double c0 = cg(l1, m1, l2, m2, lo, M);
                                constexpr double cc = (l1 == l2 && m1 < m2)
                                    ? c0 + cg(l1, m2, l2, m1, lo, M) : c0;
                                if constexpr (cc != 0.0) {
                                    constexpr float cf_ = (float)cc;
                                    gre[lo - lstart] += cf_ * p_re;   // FFMA-imm (rt=1)
                                    gim[lo - lstart] += cf_ * p_im;   // FFMA-imm (rt=1)
                                }
                            });
                        }
                    });

                    // contract with conj(F_lo^M) + CG-power norms; F_lo^M from SMEM
                    constexpr int am = M < 0 ? -M : M;
                    sfor<lstart, lomax + 1>([&](auto LOc) {
                        constexpr int lo = decltype(LOc)::value;
                        float g_re = gre[lo - lstart], g_im = gim[lo - lstart];
                        float2 f3 = myc[cpos(lo, am)];
                        float f3re, f3im;
                        if constexpr (M >= 0)      { f3re =  f3.x; f3im =  f3.y; }
                        else if constexpr (am & 1) { f3re = -f3.x; f3im =  f3.y; }
                        else                       { f3re =  f3.x; f3im = -f3.y; }
                        beta[lo - lomin] += g_re * f3re + g_im * f3im;
                        if constexpr (power_index(l1, l2, lo) >= 0) {
                            pw[lo - lomin] += g_re * g_re + g_im * g_im;
                        }
                    });
                }
            });

            // write outputs for this (l1,l2) block
            sfor<lomin, lomax + 1>([&](auto LOc) {
                constexpr int lo = decltype(LOc)::value;
                constexpr int fidx = full_index(l1, l2, lo);
                ob[fidx] = beta[lo - lomin];
                constexpr int pidx = power_index(l1, l2, lo);
                if constexpr (pidx >= 0) {
                    ob[NFULL + pidx] = pw[lo - lomin];
                }
            });
        });
    });
}

} // namespace so3

extern "C" void kernel_launch(void* const* d_in, const int* in_sizes, int n_in,
                              void* d_out, int out_size) {
    const float* cre = (const float*)d_in[0];
    const float* cim = (const float*)d_in[1];
    float* out = (float*)d_out;
    const int batch = in_sizes[0] / so3::NCOEF;
    const int blocks = (batch + so3::TPB - 1) / so3::TPB;
    so3::bispec_kernel<<<blocks, so3::TPB>>>(cre, cim, out, batch);
}